// round 3
// baseline (speedup 1.0000x reference)
#include <cuda_runtime.h>

#define Vn 55
#define Cn 64
#define Dn 64
#define Tn 128
#define Nn 64
#define NTn (Nn * Tn)          // 8192
#define VD (Vn * Dn)           // 3520
#define TOTAL (NTn * VD)       // 28,835,840

// Intermediate g in [n][t][d][v] layout (temporal kernel reads contiguous v)
__device__ float g_buf[TOTAL];

// ---------------------------------------------------------------------------
// kernelA: one block per (n,t).
//   - loads x slab [64c x 55v] into smem
//   - computes mask table (tanh) + BN1 tables in smem (self-contained prep)
//   - spatial shift + mask -> hsT[c][u]
//   - 55x64x64 GEMM, plain FFMA, 4u x 4d register tile per thread
//   - BN1 + ReLU + inverse shift -> staging -> coalesced store g[n][t][d][v]
// ---------------------------------------------------------------------------
__global__ __launch_bounds__(256) void kernelA(
    const float* __restrict__ x, const float* __restrict__ W,
    const float* __restrict__ fm, const float* __restrict__ b,
    const float* __restrict__ g1, const float* __restrict__ be1,
    const float* __restrict__ m1, const float* __restrict__ v1)
{
    __shared__ __align__(16) float xs[Cn * 56];   // x slab [c][v]; later A1 table
    __shared__ __align__(16) float ms[Cn * 56];   // mask [c][u];  later B1 table
    __shared__ __align__(16) float hsT[Cn * 56];  // shifted/masked [c][u]
    __shared__ __align__(16) float ws[Cn * Dn];   // W row-major; later out staging

    const int tid = threadIdx.x;
    const int nt = blockIdx.x;
    const int n = nt >> 7;
    const int t = nt & 127;

    // W
    for (int i = tid; i < Cn * Dn; i += 256) ws[i] = W[i];

    // x slab: xs[c*56+v] = x[n][c][t][v]
    const float* xnt = x + ((size_t)n * Cn * Tn + t) * Vn;
    for (int i = tid; i < Cn * Vn; i += 256) {
        int c = i / Vn;
        int v = i - c * Vn;
        xs[c * 56 + v] = xnt[(size_t)c * (Tn * Vn) + v];
    }

    // mask: ms[c*56+u] = tanh(fm[u*64+c]) + 1
    for (int i = tid; i < Vn * Cn; i += 256) {
        int u = i >> 6;
        int c = i & 63;
        ms[c * 56 + u] = tanhf(fm[i]) + 1.0f;
    }
    __syncthreads();

    // hsT[c][u] = xs[c][(u+c)%55] * ms[c][u]  (u=55 pad -> 0)
    for (int i = tid; i < Cn * 56; i += 256) {
        int c = i / 56;
        int u = i - c * 56;
        float val = 0.0f;
        if (u < Vn) {
            int s = u + c;
            if (s >= Vn) s -= Vn;
            if (s >= Vn) s -= Vn;
            val = xs[c * 56 + s] * ms[i];
        }
        hsT[i] = val;
    }
    __syncthreads();

    // BN1 tables into xs (A1) and ms (B1); index [u*64+d]
    for (int i = tid; i < VD; i += 256) {
        float a = g1[i] * rsqrtf(v1[i] + 1e-5f);
        xs[i] = a;
        ms[i] = be1[i] + a * (b[i & 63] - m1[i]);
    }

    // GEMM: y[u][d] = sum_c hsT[c][u] * ws[c][d]
    const int dg = tid & 15;   // d = dg*4 .. +3
    const int ut = tid >> 4;   // u = ut*4 .. +3 (active ut < 14)

    float acc[4][4];
#pragma unroll
    for (int a = 0; a < 4; a++)
#pragma unroll
        for (int j = 0; j < 4; j++) acc[a][j] = 0.0f;

    if (ut < 14) {
        const float* hp = &hsT[ut * 4];
        const float* wp = &ws[dg * 4];
#pragma unroll 8
        for (int c = 0; c < Cn; c++) {
            float4 h4 = *reinterpret_cast<const float4*>(hp + c * 56);
            float4 w4 = *reinterpret_cast<const float4*>(wp + c * Dn);
            acc[0][0] += h4.x * w4.x; acc[0][1] += h4.x * w4.y; acc[0][2] += h4.x * w4.z; acc[0][3] += h4.x * w4.w;
            acc[1][0] += h4.y * w4.x; acc[1][1] += h4.y * w4.y; acc[1][2] += h4.y * w4.z; acc[1][3] += h4.y * w4.w;
            acc[2][0] += h4.z * w4.x; acc[2][1] += h4.z * w4.y; acc[2][2] += h4.z * w4.z; acc[2][3] += h4.z * w4.w;
            acc[3][0] += h4.w * w4.x; acc[3][1] += h4.w * w4.y; acc[3][2] += h4.w * w4.z; acc[3][3] += h4.w * w4.w;
        }
    }
    __syncthreads();   // GEMM reads of ws/hsT done; BN1 tables visible

    // Epilogue: BN1 + ReLU + inverse shift; stage into ws as out_s[d*55 + (u+d)%55]
    if (ut < 14) {
#pragma unroll
        for (int uu = 0; uu < 4; uu++) {
            int u = ut * 4 + uu;
            if (u < Vn) {
#pragma unroll
                for (int dd = 0; dd < 4; dd++) {
                    int d = dg * 4 + dd;
                    int idx = u * Dn + d;
                    float y = fmaxf(xs[idx] * acc[uu][dd] + ms[idx], 0.0f);
                    int vv = u + d;
                    if (vv >= Vn) vv -= Vn;
                    if (vv >= Vn) vv -= Vn;
                    ws[d * Vn + vv] = y;
                }
            }
        }
    }
    __syncthreads();

    // Coalesced store g[n][t][d][v]
    float* gout = &g_buf[(size_t)nt * VD];
    for (int i = tid; i < VD; i += 256) gout[i] = ws[i];
}

// ---------------------------------------------------------------------------
// kernelB: temporal shift + BN2 + residual + ReLU. Fully coalesced.
// BN2 scalars computed per thread (tiny arrays, L1-resident).
// ---------------------------------------------------------------------------
__global__ __launch_bounds__(256) void kernelB(
    const float* __restrict__ x,
    const float* __restrict__ g2, const float* __restrict__ be2,
    const float* __restrict__ m2, const float* __restrict__ v2,
    float* __restrict__ out)
{
    int idx = blockIdx.x * 256 + threadIdx.x;   // < 28,835,840
    int v = idx % Vn;
    int r = idx / Vn;       // (n*64+c)*128 + t
    int t = r & 127;
    int nc = r >> 7;
    int c = nc & 63;
    int n = nc >> 6;

    float a2 = g2[c] * rsqrtf(v2[c] + 1e-5f);
    float b2 = be2[c] - a2 * m2[c];

    int tt = t + (c % 3) - 1;
    float gval = 0.0f;
    if ((unsigned)tt < (unsigned)Tn) {
        gval = g_buf[((size_t)(n * Tn + tt)) * VD + c * Vn + v];
    }
    out[idx] = fmaxf(a2 * gval + b2 + x[idx], 0.0f);
}

extern "C" void kernel_launch(void* const* d_in, const int* in_sizes, int n_in,
                              void* d_out, int out_size)
{
    const float* x   = (const float*)d_in[0];
    const float* W   = (const float*)d_in[1];
    const float* b   = (const float*)d_in[2];
    const float* fm  = (const float*)d_in[3];
    const float* g1  = (const float*)d_in[4];
    const float* be1 = (const float*)d_in[5];
    const float* m1  = (const float*)d_in[6];
    const float* v1  = (const float*)d_in[7];
    const float* g2  = (const float*)d_in[8];
    const float* be2 = (const float*)d_in[9];
    const float* m2  = (const float*)d_in[10];
    const float* v2  = (const float*)d_in[11];
    float* out = (float*)d_out;

    kernelA<<<NTn, 256>>>(x, W, fm, b, g1, be1, m1, v1);
    kernelB<<<TOTAL / 256, 256>>>(x, g2, be2, m2, v2, out);
}

// round 5
// speedup vs baseline: 1.4291x; 1.4291x over previous
#include <cuda_runtime.h>
#include <cstdint>

#define Vn 55
#define Cn 64
#define Dn 64
#define Tn 128
#define Nn 64
#define NTn 8192
#define VD 3520
#define TOTAL (NTn * VD)       // 28,835,840

__device__ float g_buf[TOTAL];     // g in [n][t][d][v]
__device__ float d_mT[4096];       // mask transposed: d_mT[k*64+u] = tanh(fm[u*64+k])+1
__device__ float d_A1T[4096];      // BN1 scale, [d*64+u]
__device__ float d_B1T[4096];      // BN1 shift (bias folded), [d*64+u]
__device__ float d_A2[Dn];
__device__ float d_B2[Dn];
__device__ float d_Wh[4160];       // W hi (tf32), [c*65+d] (pad-65 rows)
__device__ float d_Wl[4160];       // W lo residual, [c*65+d]

__device__ __forceinline__ float tf32_rna(float x) {
    unsigned u;
    asm("cvt.rna.tf32.f32 %0, %1;" : "=r"(u) : "f"(x));
    return __uint_as_float(u);
}

__device__ __forceinline__ void mma8(float* c, const unsigned* a, const unsigned* b) {
    asm volatile(
        "mma.sync.aligned.m16n8k8.row.col.f32.tf32.tf32.f32 "
        "{%0,%1,%2,%3}, {%4,%5,%6,%7}, {%8,%9}, {%0,%1,%2,%3};"
        : "+f"(c[0]), "+f"(c[1]), "+f"(c[2]), "+f"(c[3])
        : "r"(a[0]), "r"(a[1]), "r"(a[2]), "r"(a[3]), "r"(b[0]), "r"(b[1]));
}

// ---- prep: one-time tables -------------------------------------------------
__global__ __launch_bounds__(256) void prep_kernel(
    const float* __restrict__ W, const float* __restrict__ b,
    const float* __restrict__ fm,
    const float* __restrict__ g1, const float* __restrict__ be1,
    const float* __restrict__ m1, const float* __restrict__ v1,
    const float* __restrict__ g2, const float* __restrict__ be2,
    const float* __restrict__ m2, const float* __restrict__ v2)
{
    int i = blockIdx.x * 256 + threadIdx.x;   // 0..4095
    if (i < 4096) {
        // mask transposed
        int k = i >> 6, u = i & 63;
        float mval = 0.0f;
        if (u < Vn) mval = tanhf(fm[u * Cn + k]) + 1.0f;
        d_mT[i] = mval;

        // W split hi/lo, pad-65 layout: i = c*64+d
        int c = i >> 6, d = i & 63;
        float w = W[i];
        float hi = tf32_rna(w);
        float lo = tf32_rna(w - hi);
        d_Wh[c * 65 + d] = hi;
        d_Wl[c * 65 + d] = lo;
    }
    if (i < VD) {
        int u = i >> 6, d = i & 63;
        float a = g1[i] * rsqrtf(v1[i] + 1e-5f);
        d_A1T[d * 64 + u] = a;
        d_B1T[d * 64 + u] = be1[i] + a * (b[d] - m1[i]);
    }
    if (i < Dn) {
        float a = g2[i] * rsqrtf(v2[i] + 1e-5f);
        d_A2[i] = a;
        d_B2[i] = be2[i] - a * m2[i];
    }
}

// ---- kernelA: shift+mask -> tf32 mma.sync GEMM (3-pass) -> BN1+ReLU+shift --
// dyn smem (floats): hsT_h[0,3584) hsT_l[3584,7168) ws_h[7168,11328) ws_l[11328,15488)
#define SMEMA_FLOATS 15488
#define SMEMA_BYTES (SMEMA_FLOATS * 4)

__global__ __launch_bounds__(256) void kernelA(const float* __restrict__ x)
{
    extern __shared__ __align__(16) float sm[];
    float* hsT_h = sm;            // [k][u], stride 56
    float* hsT_l = sm + 3584;
    float* ws_h  = sm + 7168;     // [k][d], stride 65
    float* ws_l  = sm + 11328;

    const int tid = threadIdx.x;
    const int nt = blockIdx.x;
    const int n = nt >> 7;
    const int t = nt & 127;

    // Copy W tiles (already split + padded in prep)
    {
        float4* wh4 = (float4*)ws_h;
        float4* wl4 = (float4*)ws_l;
        const float4* gh4 = (const float4*)d_Wh;
        const float4* gl4 = (const float4*)d_Wl;
        for (int i = tid; i < 1040; i += 256) { wh4[i] = gh4[i]; wl4[i] = gl4[i]; }
    }

    // Build A = shifted/masked x, tf32 hi/lo, layout hsT[k*56+u]
    const float* xnt = x + ((size_t)n * Cn * Tn + t) * Vn;
    for (int i = tid; i < 4096; i += 256) {
        int k = i >> 6;
        int u = i & 63;
        if (u < 56) {
            float hi = 0.0f, lo = 0.0f;
            if (u < Vn) {
                int s = u + k;
                if (s >= Vn) s -= Vn;
                if (s >= Vn) s -= Vn;
                float val = xnt[(size_t)k * (Tn * Vn) + s] * d_mT[i];
                hi = tf32_rna(val);
                lo = tf32_rna(val - hi);
            }
            hsT_h[k * 56 + u] = hi;
            hsT_l[k * 56 + u] = lo;
        }
    }
    __syncthreads();

    // GEMM: y[u][d] = sum_k A[u][k] * W[k][d], M=64(55) N=64 K=64
    // warp w: m-tile = w&3 (16 u's), n-range = (w>>2)*32 (4 n8-tiles)
    const int w = tid >> 5;
    const int lane = tid & 31;
    const int lr = lane >> 2;    // group row
    const int lc = lane & 3;     // thread-in-group
    const int ub = (w & 3) * 16;
    const int nb = (w >> 2) * 32;

    float acc[4][4];
#pragma unroll
    for (int i = 0; i < 4; i++)
#pragma unroll
        for (int j = 0; j < 4; j++) acc[i][j] = 0.0f;

#pragma unroll
    for (int kk = 0; kk < 64; kk += 8) {
        const int ab = (kk + lc) * 56 + ub + lr;
        unsigned ah[4], al[4];
        ah[0] = __float_as_uint(hsT_h[ab]);
        ah[1] = __float_as_uint(hsT_h[ab + 8]);
        ah[2] = __float_as_uint(hsT_h[ab + 4 * 56]);
        ah[3] = __float_as_uint(hsT_h[ab + 4 * 56 + 8]);
        al[0] = __float_as_uint(hsT_l[ab]);
        al[1] = __float_as_uint(hsT_l[ab + 8]);
        al[2] = __float_as_uint(hsT_l[ab + 4 * 56]);
        al[3] = __float_as_uint(hsT_l[ab + 4 * 56 + 8]);
#pragma unroll
        for (int ntile = 0; ntile < 4; ntile++) {
            const int bb = (kk + lc) * 65 + nb + ntile * 8 + lr;
            unsigned bh[2], bl[2];
            bh[0] = __float_as_uint(ws_h[bb]);
            bh[1] = __float_as_uint(ws_h[bb + 4 * 65]);
            bl[0] = __float_as_uint(ws_l[bb]);
            bl[1] = __float_as_uint(ws_l[bb + 4 * 65]);
            mma8(acc[ntile], ah, bh);
            mma8(acc[ntile], al, bh);
            mma8(acc[ntile], ah, bl);
        }
    }
    __syncthreads();   // all GEMM smem reads done; reuse hsT_h as staging

    // Epilogue: BN1 + ReLU + inverse shift into stage[d*55 + (u+d)%55]
    float* stage = hsT_h;   // 3520 floats needed, 3584 available
#pragma unroll
    for (int i = 0; i < 4; i++) {
        int u = ub + lr + ((i & 2) ? 8 : 0);
        if (u < Vn) {
#pragma unroll
            for (int ntile = 0; ntile < 4; ntile++) {
                int d = nb + ntile * 8 + lc * 2 + (i & 1);
                int j = d * 64 + u;
                float y = fmaxf(d_A1T[j] * acc[ntile][i] + d_B1T[j], 0.0f);
                int vv = u + d;
                if (vv >= Vn) vv -= Vn;
                if (vv >= Vn) vv -= Vn;
                stage[d * Vn + vv] = y;
            }
        }
    }
    __syncthreads();

    // Coalesced store g[n][t][d][v]
    {
        float4* gout = (float4*)&g_buf[(size_t)nt * VD];
        const float4* ss = (const float4*)stage;
        for (int i = tid; i < 880; i += 256) gout[i] = ss[i];
    }
}

// ---- kernelB: temporal shift + BN2 + residual + ReLU (float4) --------------
__global__ __launch_bounds__(256) void kernelB(const float* __restrict__ x,
                                               float* __restrict__ out)
{
    int gid = blockIdx.x * 256 + threadIdx.x;   // < 7,208,960
    int i0 = gid * 4;
    int nc = i0 / 7040;                // (n*64+c); all 4 elems in same chunk
    int rem = i0 - nc * 7040;
    int c = nc & 63;
    int n = nc >> 6;
    float a2 = d_A2[c], b2 = d_B2[c];
    int off = (c % 3) - 1;
    const float* gb = &g_buf[(size_t)(n * Tn) * VD + c * Vn];

    float4 xv = *(const float4*)(x + i0);
    float xr[4] = {xv.x, xv.y, xv.z, xv.w};
    float r[4];
#pragma unroll
    for (int e = 0; e < 4; e++) {
        int re = rem + e;
        int t = re / 55;
        int v = re - t * 55;
        int tt = t + off;
        float gv = 0.0f;
        if ((unsigned)tt < (unsigned)Tn) gv = gb[(size_t)tt * VD + v];
        r[e] = fmaxf(a2 * gv + b2 + xr[e], 0.0f);
    }
    float4 ov = {r[0], r[1], r[2], r[3]};
    *(float4*)(out + i0) = ov;
}

extern "C" void kernel_launch(void* const* d_in, const int* in_sizes, int n_in,
                              void* d_out, int out_size)
{
    const float* x   = (const float*)d_in[0];
    const float* W   = (const float*)d_in[1];
    const float* b   = (const float*)d_in[2];
    const float* fm  = (const float*)d_in[3];
    const float* g1  = (const float*)d_in[4];
    const float* be1 = (const float*)d_in[5];
    const float* m1  = (const float*)d_in[6];
    const float* v1  = (const float*)d_in[7];
    const float* g2  = (const float*)d_in[8];
    const float* be2 = (const float*)d_in[9];
    const float* m2  = (const float*)d_in[10];
    const float* v2  = (const float*)d_in[11];
    float* out = (float*)d_out;

    cudaFuncSetAttribute(kernelA, cudaFuncAttributeMaxDynamicSharedMemorySize, SMEMA_BYTES);

    prep_kernel<<<16, 256>>>(W, b, fm, g1, be1, m1, v1, g2, be2, m2, v2);
    kernelA<<<NTn, 256, SMEMA_BYTES>>>(x);
    kernelB<<<TOTAL / 1024, 256>>>(x, out);
}

// round 6
// speedup vs baseline: 2.6350x; 1.8438x over previous
#include <cuda_runtime.h>
#include <cuda_bf16.h>
#include <cstdint>

#define Vn 55
#define Cn 64
#define Dn 64
#define Tn 128
#define Nn 64
#define NTn 8192
#define VD 3520
#define TOTAL (NTn * VD)       // 28,835,840

#define RS 72                  // padded row stride in bf16 elements (36 words)

__device__ float g_buf[TOTAL];            // g in [n][t][d][v]
__device__ float d_mT[4096];              // mask transposed: [k*64+u] = tanh(fm[u*64+k])+1
__device__ float d_A1T[4096];             // BN1 scale, [d*64+u]
__device__ float d_B1T[4096];             // BN1 shift (bias folded), [d*64+u]
__device__ float d_A2[Dn];
__device__ float d_B2[Dn];
__device__ __nv_bfloat16 d_WhB[64 * RS];  // W^T hi, [d*RS + c]
__device__ __nv_bfloat16 d_WlB[64 * RS];  // W^T lo residual

__device__ __forceinline__ void mma16(float* c, const unsigned* a, const unsigned* b) {
    asm volatile(
        "mma.sync.aligned.m16n8k16.row.col.f32.bf16.bf16.f32 "
        "{%0,%1,%2,%3}, {%4,%5,%6,%7}, {%8,%9}, {%0,%1,%2,%3};"
        : "+f"(c[0]), "+f"(c[1]), "+f"(c[2]), "+f"(c[3])
        : "r"(a[0]), "r"(a[1]), "r"(a[2]), "r"(a[3]), "r"(b[0]), "r"(b[1]));
}

// ---- prep: one-time tables -------------------------------------------------
__global__ __launch_bounds__(256) void prep_kernel(
    const float* __restrict__ W, const float* __restrict__ b,
    const float* __restrict__ fm,
    const float* __restrict__ g1, const float* __restrict__ be1,
    const float* __restrict__ m1, const float* __restrict__ v1,
    const float* __restrict__ g2, const float* __restrict__ be2,
    const float* __restrict__ m2, const float* __restrict__ v2)
{
    int i = blockIdx.x * 256 + threadIdx.x;   // 0..4095
    if (i < 4096) {
        // mask transposed: [k][u]
        int k = i >> 6, u = i & 63;
        float mval = 0.0f;
        if (u < Vn) mval = tanhf(fm[u * Cn + k]) + 1.0f;
        d_mT[i] = mval;

        // W^T split hi/lo, padded rows: i = c*64+d
        int c = i >> 6, d = i & 63;
        float w = W[i];
        __nv_bfloat16 h = __float2bfloat16(w);
        float lo = w - __bfloat162float(h);
        d_WhB[d * RS + c] = h;
        d_WlB[d * RS + c] = __float2bfloat16(lo);
    }
    if (i < VD) {
        int u = i >> 6, d = i & 63;
        float a = g1[i] * rsqrtf(v1[i] + 1e-5f);
        d_A1T[d * 64 + u] = a;
        d_B1T[d * 64 + u] = be1[i] + a * (b[d] - m1[i]);
    }
    if (i < Dn) {
        float a = g2[i] * rsqrtf(v2[i] + 1e-5f);
        d_A2[i] = a;
        d_B2[i] = be2[i] - a * m2[i];
    }
}

// ---- kernelA: shift+mask -> bf16x3 mma GEMM -> BN1+ReLU+inverse shift ------
// Static smem 36864 B: AH[0,9216) AL[9216,18432) BH[18432,27648) BL[27648,36864)
// Stage (3520 floats = 14080 B) overlays AH/AL after GEMM.
__global__ __launch_bounds__(256) void kernelA(const float* __restrict__ x)
{
    __shared__ __align__(16) char smraw[36864];
    __nv_bfloat16* AH = (__nv_bfloat16*)smraw;              // [u*RS + k]
    __nv_bfloat16* AL = AH + 64 * RS;
    __nv_bfloat16* BH = AL + 64 * RS;                       // [d*RS + k]
    __nv_bfloat16* BL = BH + 64 * RS;

    const int tid = threadIdx.x;
    const int nt = blockIdx.x;
    const int n = nt >> 7;
    const int t = nt & 127;

    // Copy W tiles (pre-split/padded): 9216 B each = 576 float4
    {
        float4* bh4 = (float4*)BH;
        float4* bl4 = (float4*)BL;
        const float4* gh4 = (const float4*)d_WhB;
        const float4* gl4 = (const float4*)d_WlB;
        for (int i = tid; i < 576; i += 256) { bh4[i] = gh4[i]; bl4[i] = gl4[i]; }
    }

    // Build A: A[u][k] = x[n,k,t,(u+k)%55] * mT[k][u], bf16 hi/lo split
    const float* xnt = x + ((size_t)n * Cn * Tn + t) * Vn;
    for (int i = tid; i < 4096; i += 256) {
        int k = i >> 6;
        int u = i & 63;
        float val = 0.0f;
        if (u < Vn) {
            int s = u + k;
            if (s >= Vn) s -= Vn;
            if (s >= Vn) s -= Vn;
            val = xnt[(size_t)k * (Tn * Vn) + s] * d_mT[i];
        }
        __nv_bfloat16 h = __float2bfloat16(val);
        float lo = val - __bfloat162float(h);
        AH[u * RS + k] = h;
        AL[u * RS + k] = __float2bfloat16(lo);
    }
    __syncthreads();

    // GEMM: y[u][d] = sum_k A[u][k] * WT[d][k].  M=64 N=64 K=64.
    // warp w: rows ub..ub+15 (w&3), cols nb..nb+31 (w>>2), 4 n8-tiles.
    const int w = tid >> 5;
    const int lane = tid & 31;
    const int lr = lane >> 2;    // group (0..7)
    const int lc = lane & 3;     // thread-in-group (0..3)
    const int ub = (w & 3) * 16;
    const int nb = (w >> 2) * 32;

    const unsigned* AHw = (const unsigned*)AH;   // word view (36 words/row)
    const unsigned* ALw = (const unsigned*)AL;
    const unsigned* BHw = (const unsigned*)BH;
    const unsigned* BLw = (const unsigned*)BL;

    float acc[4][4];
#pragma unroll
    for (int i = 0; i < 4; i++)
#pragma unroll
        for (int j = 0; j < 4; j++) acc[i][j] = 0.0f;

#pragma unroll
    for (int s = 0; s < 4; s++) {               // k0 = s*16
        const int abase = (ub + lr) * 36 + s * 8 + lc;
        unsigned ah[4], al[4];
        ah[0] = AHw[abase];
        ah[1] = AHw[abase + 8 * 36];
        ah[2] = AHw[abase + 4];
        ah[3] = AHw[abase + 8 * 36 + 4];
        al[0] = ALw[abase];
        al[1] = ALw[abase + 8 * 36];
        al[2] = ALw[abase + 4];
        al[3] = ALw[abase + 8 * 36 + 4];
#pragma unroll
        for (int ntile = 0; ntile < 4; ntile++) {
            const int bbase = (nb + ntile * 8 + lr) * 36 + s * 8 + lc;
            unsigned bh[2], bl[2];
            bh[0] = BHw[bbase];
            bh[1] = BHw[bbase + 4];
            bl[0] = BLw[bbase];
            bl[1] = BLw[bbase + 4];
            mma16(acc[ntile], ah, bh);
            mma16(acc[ntile], ah, bl);
            mma16(acc[ntile], al, bh);
        }
    }
    __syncthreads();   // GEMM smem reads done; reuse A region as staging

    // Epilogue: BN1 + ReLU + inverse shift into stage[d*55 + (u+d)%55]
    float* stage = (float*)smraw;
#pragma unroll
    for (int i = 0; i < 4; i++) {
        int u = ub + lr + ((i & 2) ? 8 : 0);
        if (u < Vn) {
#pragma unroll
            for (int ntile = 0; ntile < 4; ntile++) {
                int d = nb + ntile * 8 + lc * 2 + (i & 1);
                int j = d * 64 + u;
                float y = fmaxf(d_A1T[j] * acc[ntile][i] + d_B1T[j], 0.0f);
                int vv = u + d;
                if (vv >= Vn) vv -= Vn;
                if (vv >= Vn) vv -= Vn;
                stage[d * Vn + vv] = y;
            }
        }
    }
    __syncthreads();

    // Coalesced store g[n][t][d][v]
    {
        float4* gout = (float4*)&g_buf[(size_t)nt * VD];
        const float4* ss = (const float4*)stage;
        for (int i = tid; i < 880; i += 256) gout[i] = ss[i];
    }
}

// ---- kernelB: temporal shift + BN2 + residual + ReLU (float4) --------------
__global__ __launch_bounds__(256) void kernelB(const float* __restrict__ x,
                                               float* __restrict__ out)
{
    int gid = blockIdx.x * 256 + threadIdx.x;   // < 7,208,960
    int i0 = gid * 4;
    int nc = i0 / 7040;                // (n*64+c); all 4 elems in same chunk
    int rem = i0 - nc * 7040;
    int c = nc & 63;
    int n = nc >> 6;
    float a2 = d_A2[c], b2 = d_B2[c];
    int off = (c % 3) - 1;
    const float* gb = &g_buf[(size_t)(n * Tn) * VD + c * Vn];

    float4 xv = *(const float4*)(x + i0);
    float xr[4] = {xv.x, xv.y, xv.z, xv.w};
    float r[4];
#pragma unroll
    for (int e = 0; e < 4; e++) {
        int re = rem + e;
        int t = re / 55;
        int v = re - t * 55;
        int tt = t + off;
        float gv = 0.0f;
        if ((unsigned)tt < (unsigned)Tn) gv = gb[(size_t)tt * VD + v];
        r[e] = fmaxf(a2 * gv + b2 + xr[e], 0.0f);
    }
    float4 ov = {r[0], r[1], r[2], r[3]};
    *(float4*)(out + i0) = ov;
}

extern "C" void kernel_launch(void* const* d_in, const int* in_sizes, int n_in,
                              void* d_out, int out_size)
{
    const float* x   = (const float*)d_in[0];
    const float* W   = (const float*)d_in[1];
    const float* b   = (const float*)d_in[2];
    const float* fm  = (const float*)d_in[3];
    const float* g1  = (const float*)d_in[4];
    const float* be1 = (const float*)d_in[5];
    const float* m1  = (const float*)d_in[6];
    const float* v1  = (const float*)d_in[7];
    const float* g2  = (const float*)d_in[8];
    const float* be2 = (const float*)d_in[9];
    const float* m2  = (const float*)d_in[10];
    const float* v2  = (const float*)d_in[11];
    float* out = (float*)d_out;

    prep_kernel<<<16, 256>>>(W, b, fm, g1, be1, m1, v1, g2, be2, m2, v2);
    kernelA<<<NTn, 256>>>(x);
    kernelB<<<TOTAL / 1024, 256>>>(x, out);
}